// round 7
// baseline (speedup 1.0000x reference)
#include <cuda_runtime.h>
#include <math_constants.h>
#include <cstdint>

// Problem shape (fixed by the dataset)
#define BB 4
#define HH 16
#define SS 2048
#define DD 64

#define BM 128   // query rows per CTA (8 warps x 16 rows)
#define BN 64    // key/value columns per tile
#define SQ 72    // smem row stride (floats): stride mod 32 == 8 -> fragment loads conflict-free

// Dynamic smem layout (floats) — hi/lo tf32 planes:
#define QH_OFF 0                       // [BM][SQ] Q hi   (row r, col d)   9216
#define QL_OFF (QH_OFF + BM*SQ)        // [BM][SQ] Q lo                    9216
#define KH_OFF (QL_OFF + BM*SQ)        // [DD][SQ] K hi   (row d, col s)   4608
#define KL_OFF (KH_OFF + DD*SQ)        // [DD][SQ] K lo                    4608
#define VH_OFF (KL_OFF + DD*SQ)        // [BN][SQ] V hi   (row s, col d)   4608
#define VL_OFF (VH_OFF + BN*SQ)        // [BN][SQ] V lo                    4608
#define PH_OFF (VL_OFF + BN*SQ)        // [BM][SQ] P hi   (row r, col s)   9216
#define PL_OFF (PH_OFF + BM*SQ)        // [BM][SQ] P lo                    9216
#define SMEM_FLOATS (PL_OFF + BM*SQ)   // 55296 floats = 221,184 B

__device__ __forceinline__ uint32_t tf32_rna(float x) {
    uint32_t u; asm("cvt.rna.tf32.f32 %0, %1;" : "=r"(u) : "f"(x)); return u;
}
__device__ __forceinline__ void split2(float x, float &h, float &l) {
    uint32_t uh = tf32_rna(x);
    h = __uint_as_float(uh);
    l = __uint_as_float(tf32_rna(x - h));
}
__device__ __forceinline__ uint32_t fb(float x) { return __float_as_uint(x); }

__device__ __forceinline__ void mma8(float* c,
    uint32_t a0, uint32_t a1, uint32_t a2, uint32_t a3,
    uint32_t b0, uint32_t b1)
{
    asm volatile(
        "mma.sync.aligned.m16n8k8.row.col.f32.tf32.tf32.f32 "
        "{%0,%1,%2,%3},{%4,%5,%6,%7},{%8,%9},{%0,%1,%2,%3};"
        : "+f"(c[0]), "+f"(c[1]), "+f"(c[2]), "+f"(c[3])
        : "r"(a0), "r"(a1), "r"(a2), "r"(a3), "r"(b0), "r"(b1));
}

__global__ __launch_bounds__(256, 1)
void attn_mma_kernel(const float* __restrict__ q,
                     const float* __restrict__ k,
                     const float* __restrict__ v,
                     const int*   __restrict__ mask,
                     float* __restrict__ out_o,   // may be null
                     float* __restrict__ out_s)   // may be null
{
    extern __shared__ float sm[];
    float* qh = sm + QH_OFF;  float* ql = sm + QL_OFF;
    float* kh = sm + KH_OFF;  float* kl = sm + KL_OFF;
    float* vh = sm + VH_OFF;  float* vl = sm + VL_OFF;
    float* ph = sm + PH_OFF;  float* pl = sm + PL_OFF;

    const int tid  = threadIdx.x;
    const int lane = tid & 31;
    const int w    = tid >> 5;       // warp 0..7 -> rows 16w..16w+15
    const int g    = lane >> 2;      // group 0..7
    const int t    = lane & 3;       // thread-in-group 0..3

    const int rb = blockIdx.x;
    const int h  = blockIdx.y;
    const int b  = blockIdx.z;

    const size_t bh = (size_t)b * HH + h;
    const float* qp = q + (bh * SS + (size_t)rb * BM) * DD;   // [BM][DD]
    const float* kp = k + bh * (size_t)DD * SS;               // [DD][SS]
    const float* vp = v + bh * (size_t)SS * DD;               // [SS][DD]
    const int*   mp = mask + ((size_t)b * SS + (size_t)rb * BM) * SS;  // [BM][SS]
    float* osp = out_s ? (out_s + (bh * SS + (size_t)rb * BM) * SS) : (float*)0;

    // ---- Load + split Q tile (128 x 64) once ----
    #pragma unroll
    for (int it = 0; it < 8; ++it) {
        int id4 = tid + it * 256;
        int r  = id4 >> 4;
        int d4 = (id4 & 15) * 4;
        float4 qv = *(const float4*)(qp + (size_t)r * DD + d4);
        float4 hv, lv;
        split2(qv.x, hv.x, lv.x); split2(qv.y, hv.y, lv.y);
        split2(qv.z, hv.z, lv.z); split2(qv.w, hv.w, lv.w);
        *(float4*)(qh + r * SQ + d4) = hv;
        *(float4*)(ql + r * SQ + d4) = lv;
    }

    const int row_l0 = 16 * w + g;
    const int row_l1 = row_l0 + 8;

    float oacc[8][4];
    float m0 = -CUDART_INF_F, m1 = -CUDART_INF_F, l0 = 0.f, l1 = 0.f;
    #pragma unroll
    for (int j = 0; j < 8; ++j)
        oacc[j][0] = oacc[j][1] = oacc[j][2] = oacc[j][3] = 0.f;

    for (int jt = 0; jt < SS / BN; ++jt) {
        const int s0 = jt * BN;

        __syncthreads();   // previous tile's consumers done before overwrite
        // ---- Load + split K and V tiles ----
        #pragma unroll
        for (int it = 0; it < 4; ++it) {
            int id4 = tid + it * 256;
            int r  = id4 >> 4;             // 0..63
            int c4 = (id4 & 15) * 4;
            float4 kv = *(const float4*)(kp + (size_t)r * SS + s0 + c4);
            float4 vv = *(const float4*)(vp + (size_t)(s0 + r) * DD + c4);
            float4 khv, klv, vhv, vlv;
            split2(kv.x, khv.x, klv.x); split2(kv.y, khv.y, klv.y);
            split2(kv.z, khv.z, klv.z); split2(kv.w, khv.w, klv.w);
            split2(vv.x, vhv.x, vlv.x); split2(vv.y, vhv.y, vlv.y);
            split2(vv.z, vhv.z, vlv.z); split2(vv.w, vhv.w, vlv.w);
            *(float4*)(kh + r * SQ + c4) = khv;
            *(float4*)(kl + r * SQ + c4) = klv;
            *(float4*)(vh + r * SQ + c4) = vhv;
            *(float4*)(vl + r * SQ + c4) = vlv;
        }
        __syncthreads();

        // ---- S = Q K : 16x64 per warp, 3xTF32, no cvt in loop ----
        float sacc[8][4];
        #pragma unroll
        for (int j = 0; j < 8; ++j)
            sacc[j][0] = sacc[j][1] = sacc[j][2] = sacc[j][3] = 0.f;

        {
            const float* q0h = qh + row_l0 * SQ;  const float* q0l = ql + row_l0 * SQ;
            const float* q1h = qh + row_l1 * SQ;  const float* q1l = ql + row_l1 * SQ;
            #pragma unroll 1
            for (int k0 = 0; k0 < DD; k0 += 8) {
                uint32_t a0h = fb(q0h[k0 + t]),     a1h = fb(q1h[k0 + t]);
                uint32_t a2h = fb(q0h[k0 + t + 4]), a3h = fb(q1h[k0 + t + 4]);
                uint32_t a0l = fb(q0l[k0 + t]),     a1l = fb(q1l[k0 + t]);
                uint32_t a2l = fb(q0l[k0 + t + 4]), a3l = fb(q1l[k0 + t + 4]);
                const float* kbh  = kh + (k0 + t) * SQ + g;
                const float* kbh4 = kh + (k0 + t + 4) * SQ + g;
                const float* kbl  = kl + (k0 + t) * SQ + g;
                const float* kbl4 = kl + (k0 + t + 4) * SQ + g;
                #pragma unroll
                for (int j = 0; j < 8; ++j) {
                    uint32_t b0h = fb(kbh[8 * j]), b1h = fb(kbh4[8 * j]);
                    uint32_t b0l = fb(kbl[8 * j]), b1l = fb(kbl4[8 * j]);
                    mma8(sacc[j], a0h, a1h, a2h, a3h, b0h, b1h);
                    mma8(sacc[j], a0h, a1h, a2h, a3h, b0l, b1l);
                    mma8(sacc[j], a0l, a1l, a2l, a3l, b0h, b1h);
                }
            }
        }

        // ---- Mask, scale, store scores, intra-warp online softmax ----
        float rmax0 = -CUDART_INF_F, rmax1 = -CUDART_INF_F;
        const int coff0 = s0 + 2 * t;
        #pragma unroll
        for (int j = 0; j < 8; ++j) {
            const int coff = coff0 + 8 * j;
            int2 mr0 = *(const int2*)(mp + (size_t)row_l0 * SS + coff);
            int2 mr1 = *(const int2*)(mp + (size_t)row_l1 * SS + coff);
            float s00 = (mr0.x == 0) ? -1e10f : sacc[j][0] * 0.125f;
            float s01 = (mr0.y == 0) ? -1e10f : sacc[j][1] * 0.125f;
            float s10 = (mr1.x == 0) ? -1e10f : sacc[j][2] * 0.125f;
            float s11 = (mr1.y == 0) ? -1e10f : sacc[j][3] * 0.125f;
            if (osp) {
                *(float2*)(osp + (size_t)row_l0 * SS + coff) = make_float2(s00, s01);
                *(float2*)(osp + (size_t)row_l1 * SS + coff) = make_float2(s10, s11);
            }
            sacc[j][0] = s00; sacc[j][1] = s01; sacc[j][2] = s10; sacc[j][3] = s11;
            rmax0 = fmaxf(rmax0, fmaxf(s00, s01));
            rmax1 = fmaxf(rmax1, fmaxf(s10, s11));
        }
        rmax0 = fmaxf(rmax0, __shfl_xor_sync(0xffffffffu, rmax0, 1));
        rmax0 = fmaxf(rmax0, __shfl_xor_sync(0xffffffffu, rmax0, 2));
        rmax1 = fmaxf(rmax1, __shfl_xor_sync(0xffffffffu, rmax1, 1));
        rmax1 = fmaxf(rmax1, __shfl_xor_sync(0xffffffffu, rmax1, 2));

        float mn0 = fmaxf(m0, rmax0), mn1 = fmaxf(m1, rmax1);
        float corr0 = __expf(m0 - mn0), corr1 = __expf(m1 - mn1);
        m0 = mn0; m1 = mn1;

        float rs0 = 0.f, rs1 = 0.f;
        float* p0h = ph + row_l0 * SQ + 2 * t;  float* p0l = pl + row_l0 * SQ + 2 * t;
        float* p1h = ph + row_l1 * SQ + 2 * t;  float* p1l = pl + row_l1 * SQ + 2 * t;
        #pragma unroll
        for (int j = 0; j < 8; ++j) {
            float p00 = __expf(sacc[j][0] - mn0);
            float p01 = __expf(sacc[j][1] - mn0);
            float p10 = __expf(sacc[j][2] - mn1);
            float p11 = __expf(sacc[j][3] - mn1);
            rs0 += p00 + p01; rs1 += p10 + p11;
            float h00, l00, h01, l01, h10, l10, h11, l11;
            split2(p00, h00, l00); split2(p01, h01, l01);
            split2(p10, h10, l10); split2(p11, h11, l11);
            *(float2*)(p0h + 8 * j) = make_float2(h00, h01);
            *(float2*)(p0l + 8 * j) = make_float2(l00, l01);
            *(float2*)(p1h + 8 * j) = make_float2(h10, h11);
            *(float2*)(p1l + 8 * j) = make_float2(l10, l11);
        }
        rs0 += __shfl_xor_sync(0xffffffffu, rs0, 1);
        rs0 += __shfl_xor_sync(0xffffffffu, rs0, 2);
        rs1 += __shfl_xor_sync(0xffffffffu, rs1, 1);
        rs1 += __shfl_xor_sync(0xffffffffu, rs1, 2);
        l0 = l0 * corr0 + rs0;
        l1 = l1 * corr1 + rs1;
        #pragma unroll
        for (int j = 0; j < 8; ++j) {
            oacc[j][0] *= corr0; oacc[j][1] *= corr0;
            oacc[j][2] *= corr1; oacc[j][3] *= corr1;
        }
        __syncwarp();   // ps rows are warp-private; order STS -> LDS within warp

        // ---- O += P V : 16x64 per warp, 3xTF32, no cvt in loop ----
        {
            const float* pr0h = ph + row_l0 * SQ;  const float* pr0l = pl + row_l0 * SQ;
            const float* pr1h = ph + row_l1 * SQ;  const float* pr1l = pl + row_l1 * SQ;
            #pragma unroll 1
            for (int k0 = 0; k0 < BN; k0 += 8) {
                uint32_t a0h = fb(pr0h[k0 + t]),     a1h = fb(pr1h[k0 + t]);
                uint32_t a2h = fb(pr0h[k0 + t + 4]), a3h = fb(pr1h[k0 + t + 4]);
                uint32_t a0l = fb(pr0l[k0 + t]),     a1l = fb(pr1l[k0 + t]);
                uint32_t a2l = fb(pr0l[k0 + t + 4]), a3l = fb(pr1l[k0 + t + 4]);
                const float* vbh  = vh + (k0 + t) * SQ + g;
                const float* vbh4 = vh + (k0 + t + 4) * SQ + g;
                const float* vbl  = vl + (k0 + t) * SQ + g;
                const float* vbl4 = vl + (k0 + t + 4) * SQ + g;
                #pragma unroll
                for (int j = 0; j < 8; ++j) {
                    uint32_t b0h = fb(vbh[8 * j]), b1h = fb(vbh4[8 * j]);
                    uint32_t b0l = fb(vbl[8 * j]), b1l = fb(vbl4[8 * j]);
                    mma8(oacc[j], a0h, a1h, a2h, a3h, b0h, b1h);
                    mma8(oacc[j], a0h, a1h, a2h, a3h, b0l, b1l);
                    mma8(oacc[j], a0l, a1l, a2l, a3l, b0h, b1h);
                }
            }
        }
    }

    // ---- Normalize and write O ----
    if (out_o) {
        float inv0 = 1.0f / l0, inv1 = 1.0f / l1;
        float* op = out_o + (bh * SS + (size_t)rb * BM) * DD;
        #pragma unroll
        for (int j = 0; j < 8; ++j) {
            int dc = 8 * j + 2 * t;
            *(float2*)(op + (size_t)row_l0 * DD + dc) =
                make_float2(oacc[j][0] * inv0, oacc[j][1] * inv0);
            *(float2*)(op + (size_t)row_l1 * DD + dc) =
                make_float2(oacc[j][2] * inv1, oacc[j][3] * inv1);
        }
    }
}

extern "C" void kernel_launch(void* const* d_in, const int* in_sizes, int n_in,
                              void* d_out, int out_size)
{
    const float* q    = (const float*)d_in[0];
    const float* k    = (const float*)d_in[1];
    const float* v    = (const float*)d_in[2];
    const int*   mask = (const int*)  d_in[3];

    const long long OUT_O_N = (long long)BB * HH * SS * DD;   // 8388608
    const long long OUT_S_N = (long long)BB * HH * SS * SS;   // 268435456

    float* o_ptr = 0;
    float* s_ptr = 0;
    if ((long long)out_size == OUT_O_N + OUT_S_N) {
        o_ptr = (float*)d_out;
        s_ptr = (float*)d_out + OUT_O_N;
    } else if ((long long)out_size == OUT_O_N) {
        o_ptr = (float*)d_out;
    } else if ((long long)out_size == OUT_S_N) {
        s_ptr = (float*)d_out;
    } else {
        o_ptr = (float*)d_out;   // fallback: at least produce the primary output
    }

    const int smem_bytes = SMEM_FLOATS * (int)sizeof(float);  // 221,184 B
    cudaFuncSetAttribute(attn_mma_kernel,
                         cudaFuncAttributeMaxDynamicSharedMemorySize, smem_bytes);

    dim3 grid(SS / BM, HH, BB);   // (16, 16, 4) = 1024 CTAs
    dim3 block(256);
    attn_mma_kernel<<<grid, block, smem_bytes>>>(q, k, v, mask, o_ptr, s_ptr);
}

// round 9
// speedup vs baseline: 1.0624x; 1.0624x over previous
#include <cuda_runtime.h>
#include <math_constants.h>
#include <cstdint>

// Problem shape (fixed by the dataset)
#define BB 4
#define HH 16
#define SS 2048
#define DD 64

#define BM 128   // query rows per CTA (8 warps x 16 rows)
#define BN 32    // key/value columns per tile
#define SQ 72    // stride for 64-wide rows (mod 32 == 8 -> conflict-free frags)
#define SK 40    // stride for 32-wide rows (mod 32 == 8)

// Dynamic smem layout (floats):
#define QS_OFF 0                        // [BM][SQ] Q fp32 (row r, col d)    9216
#define KH_OFF (QS_OFF + BM*SQ)         // [DD][SK] K hi   (row d, col s)    2560
#define KL_OFF (KH_OFF + DD*SK)         // [DD][SK] K lo                     2560
#define VH_OFF (KL_OFF + DD*SK)         // [BN][SQ] V hi   (row s, col d)    2304
#define VL_OFF (VH_OFF + BN*SQ)         // [BN][SQ] V lo                     2304
#define PS_OFF (VL_OFF + BN*SQ)         // [BM][SK] P fp32 (row r, col s)    5120
#define SMEM_FLOATS (PS_OFF + BM*SK)    // 24064 floats = 96,256 B

__device__ __forceinline__ uint32_t tf32_rna(float x) {
    uint32_t u; asm("cvt.rna.tf32.f32 %0, %1;" : "=r"(u) : "f"(x)); return u;
}
__device__ __forceinline__ void split2(float x, float &h, float &l) {
    h = __uint_as_float(tf32_rna(x));
    l = __uint_as_float(tf32_rna(x - h));
}
__device__ __forceinline__ uint32_t fb(float x) { return __float_as_uint(x); }

__device__ __forceinline__ void mma8(float* c,
    uint32_t a0, uint32_t a1, uint32_t a2, uint32_t a3,
    uint32_t b0, uint32_t b1)
{
    asm volatile(
        "mma.sync.aligned.m16n8k8.row.col.f32.tf32.tf32.f32 "
        "{%0,%1,%2,%3},{%4,%5,%6,%7},{%8,%9},{%0,%1,%2,%3};"
        : "+f"(c[0]), "+f"(c[1]), "+f"(c[2]), "+f"(c[3])
        : "r"(a0), "r"(a1), "r"(a2), "r"(a3), "r"(b0), "r"(b1));
}

__global__ __launch_bounds__(256, 2)
void attn_mma_kernel(const float* __restrict__ q,
                     const float* __restrict__ k,
                     const float* __restrict__ v,
                     const int*   __restrict__ mask,
                     float* __restrict__ out_o,   // may be null
                     float* __restrict__ out_s)   // may be null
{
    extern __shared__ float sm[];
    float* qs = sm + QS_OFF;
    float* kh = sm + KH_OFF;  float* kl = sm + KL_OFF;
    float* vh = sm + VH_OFF;  float* vl = sm + VL_OFF;
    float* ps = sm + PS_OFF;

    const int tid  = threadIdx.x;
    const int lane = tid & 31;
    const int w    = tid >> 5;       // warp 0..7 -> rows 16w..16w+15
    const int g    = lane >> 2;      // group 0..7
    const int t    = lane & 3;       // thread-in-group 0..3

    const int rb = blockIdx.x;
    const int h  = blockIdx.y;
    const int b  = blockIdx.z;

    const size_t bh = (size_t)b * HH + h;
    const float* qp = q + (bh * SS + (size_t)rb * BM) * DD;   // [BM][DD]
    const float* kp = k + bh * (size_t)DD * SS;               // [DD][SS]
    const float* vp = v + bh * (size_t)SS * DD;               // [SS][DD]
    const int*   mp = mask + ((size_t)b * SS + (size_t)rb * BM) * SS;  // [BM][SS]
    float* osp = out_s ? (out_s + (bh * SS + (size_t)rb * BM) * SS) : (float*)0;

    // ---- Load Q tile (128 rows x 16 float4 = 2048 float4s), fp32, once ----
    #pragma unroll
    for (int it = 0; it < 8; ++it) {
        int id4 = tid + it * 256;
        int r  = id4 >> 4;
        int d4 = (id4 & 15) * 4;
        *(float4*)(qs + r * SQ + d4) = *(const float4*)(qp + (size_t)r * DD + d4);
    }

    const int row_l0 = 16 * w + g;
    const int row_l1 = row_l0 + 8;
    const int* mrow0 = mp + (size_t)row_l0 * SS;
    const int* mrow1 = mp + (size_t)row_l1 * SS;

    float oacc[8][4];
    float m0 = -CUDART_INF_F, m1 = -CUDART_INF_F, l0 = 0.f, l1 = 0.f;
    #pragma unroll
    for (int j = 0; j < 8; ++j)
        oacc[j][0] = oacc[j][1] = oacc[j][2] = oacc[j][3] = 0.f;

    for (int jt = 0; jt < SS / BN; ++jt) {
        const int s0 = jt * BN;

        // Prefetch this tile's mask rows (one 128B line = full BN row)
        if (t == 0) {
            asm volatile("prefetch.global.L1 [%0];" :: "l"(mrow0 + s0));
            asm volatile("prefetch.global.L1 [%0];" :: "l"(mrow1 + s0));
        }

        __syncthreads();   // previous tile's consumers done before overwrite
        // ---- Load + split K tile [64 d][32 s] into hi/lo planes ----
        #pragma unroll
        for (int it = 0; it < 2; ++it) {
            int id4 = tid + it * 256;
            int r  = id4 >> 3;             // 0..63 (d)
            int c4 = (id4 & 7) * 4;        // 0..28 (s)
            float4 kv = *(const float4*)(kp + (size_t)r * SS + s0 + c4);
            float4 hv, lv;
            split2(kv.x, hv.x, lv.x); split2(kv.y, hv.y, lv.y);
            split2(kv.z, hv.z, lv.z); split2(kv.w, hv.w, lv.w);
            *(float4*)(kh + r * SK + c4) = hv;
            *(float4*)(kl + r * SK + c4) = lv;
        }
        // ---- Load + split V tile [32 s][64 d] into hi/lo planes ----
        #pragma unroll
        for (int it = 0; it < 2; ++it) {
            int id4 = tid + it * 256;
            int r  = id4 >> 4;             // 0..31 (s)
            int c4 = (id4 & 15) * 4;       // 0..60 (d)
            float4 vv = *(const float4*)(vp + (size_t)(s0 + r) * DD + c4);
            float4 hv, lv;
            split2(vv.x, hv.x, lv.x); split2(vv.y, hv.y, lv.y);
            split2(vv.z, hv.z, lv.z); split2(vv.w, hv.w, lv.w);
            *(float4*)(vh + r * SQ + c4) = hv;
            *(float4*)(vl + r * SQ + c4) = lv;
        }
        __syncthreads();

        // ---- S = Q K : 16x32 per warp, 3xTF32, A split inline ----
        float sacc[4][4];
        #pragma unroll
        for (int j = 0; j < 4; ++j)
            sacc[j][0] = sacc[j][1] = sacc[j][2] = sacc[j][3] = 0.f;

        {
            const float* q0 = qs + row_l0 * SQ;
            const float* q1 = qs + row_l1 * SQ;
            #pragma unroll 1
            for (int k0 = 0; k0 < DD; k0 += 8) {
                float a0h, a0l, a1h, a1l, a2h, a2l, a3h, a3l;
                split2(q0[k0 + t],     a0h, a0l);
                split2(q1[k0 + t],     a1h, a1l);
                split2(q0[k0 + t + 4], a2h, a2l);
                split2(q1[k0 + t + 4], a3h, a3l);
                const float* kbh  = kh + (k0 + t) * SK + g;
                const float* kbh4 = kh + (k0 + t + 4) * SK + g;
                const float* kbl  = kl + (k0 + t) * SK + g;
                const float* kbl4 = kl + (k0 + t + 4) * SK + g;
                #pragma unroll
                for (int j = 0; j < 4; ++j) {
                    uint32_t b0h = fb(kbh[8 * j]), b1h = fb(kbh4[8 * j]);
                    uint32_t b0l = fb(kbl[8 * j]), b1l = fb(kbl4[8 * j]);
                    mma8(sacc[j], fb(a0h), fb(a1h), fb(a2h), fb(a3h), b0h, b1h);
                    mma8(sacc[j], fb(a0h), fb(a1h), fb(a2h), fb(a3h), b0l, b1l);
                    mma8(sacc[j], fb(a0l), fb(a1l), fb(a2l), fb(a3l), b0h, b1h);
                }
            }
        }

        // ---- Mask, scale, store scores (streaming), online softmax ----
        float rmax0 = -CUDART_INF_F, rmax1 = -CUDART_INF_F;
        #pragma unroll
        for (int j = 0; j < 4; ++j) {
            const int coff = s0 + 2 * t + 8 * j;
            int2 mr0 = *(const int2*)(mrow0 + coff);
            int2 mr1 = *(const int2*)(mrow1 + coff);
            float s00 = (mr0.x == 0) ? -1e10f : sacc[j][0] * 0.125f;
            float s01 = (mr0.y == 0) ? -1e10f : sacc[j][1] * 0.125f;
            float s10 = (mr1.x == 0) ? -1e10f : sacc[j][2] * 0.125f;
            float s11 = (mr1.y == 0) ? -1e10f : sacc[j][3] * 0.125f;
            if (osp) {
                __stcs((float2*)(osp + (size_t)row_l0 * SS + coff), make_float2(s00, s01));
                __stcs((float2*)(osp + (size_t)row_l1 * SS + coff), make_float2(s10, s11));
            }
            sacc[j][0] = s00; sacc[j][1] = s01; sacc[j][2] = s10; sacc[j][3] = s11;
            rmax0 = fmaxf(rmax0, fmaxf(s00, s01));
            rmax1 = fmaxf(rmax1, fmaxf(s10, s11));
        }
        rmax0 = fmaxf(rmax0, __shfl_xor_sync(0xffffffffu, rmax0, 1));
        rmax0 = fmaxf(rmax0, __shfl_xor_sync(0xffffffffu, rmax0, 2));
        rmax1 = fmaxf(rmax1, __shfl_xor_sync(0xffffffffu, rmax1, 1));
        rmax1 = fmaxf(rmax1, __shfl_xor_sync(0xffffffffu, rmax1, 2));

        float mn0 = fmaxf(m0, rmax0), mn1 = fmaxf(m1, rmax1);
        float corr0 = __expf(m0 - mn0), corr1 = __expf(m1 - mn1);
        m0 = mn0; m1 = mn1;

        float rs0 = 0.f, rs1 = 0.f;
        float* p0 = ps + row_l0 * SK + 2 * t;
        float* p1 = ps + row_l1 * SK + 2 * t;
        #pragma unroll
        for (int j = 0; j < 4; ++j) {
            float p00 = __expf(sacc[j][0] - mn0);
            float p01 = __expf(sacc[j][1] - mn0);
            float p10 = __expf(sacc[j][2] - mn1);
            float p11 = __expf(sacc[j][3] - mn1);
            rs0 += p00 + p01; rs1 += p10 + p11;
            *(float2*)(p0 + 8 * j) = make_float2(p00, p01);
            *(float2*)(p1 + 8 * j) = make_float2(p10, p11);
        }
        rs0 += __shfl_xor_sync(0xffffffffu, rs0, 1);
        rs0 += __shfl_xor_sync(0xffffffffu, rs0, 2);
        rs1 += __shfl_xor_sync(0xffffffffu, rs1, 1);
        rs1 += __shfl_xor_sync(0xffffffffu, rs1, 2);
        l0 = l0 * corr0 + rs0;
        l1 = l1 * corr1 + rs1;
        #pragma unroll
        for (int j = 0; j < 8; ++j) {
            oacc[j][0] *= corr0; oacc[j][1] *= corr0;
            oacc[j][2] *= corr1; oacc[j][3] *= corr1;
        }
        __syncwarp();   // ps rows warp-private: order STS -> LDS within warp

        // ---- O += P V : 16x64 per warp, 3xTF32, A(P) split inline ----
        {
            const float* pr0 = ps + row_l0 * SK;
            const float* pr1 = ps + row_l1 * SK;
            #pragma unroll 1
            for (int k0 = 0; k0 < BN; k0 += 8) {
                float a0h, a0l, a1h, a1l, a2h, a2l, a3h, a3l;
                split2(pr0[k0 + t],     a0h, a0l);
                split2(pr1[k0 + t],     a1h, a1l);
                split2(pr0[k0 + t + 4], a2h, a2l);
                split2(pr1[k0 + t + 4], a3h, a3l);
                const float* vbh  = vh + (k0 + t) * SQ + g;
                const float* vbh4 = vh + (k0 + t + 4) * SQ + g;
                const float* vbl  = vl + (k0 + t) * SQ + g;
                const float* vbl4 = vl + (k0 + t + 4) * SQ + g;
                #pragma unroll
                for (int j = 0; j < 8; ++j) {
                    uint32_t b0h = fb(vbh[8 * j]), b1h = fb(vbh4[8 * j]);
                    uint32_t b0l = fb(vbl[8 * j]), b1l = fb(vbl4[8 * j]);
                    mma8(oacc[j], fb(a0h), fb(a1h), fb(a2h), fb(a3h), b0h, b1h);
                    mma8(oacc[j], fb(a0h), fb(a1h), fb(a2h), fb(a3h), b0l, b1l);
                    mma8(oacc[j], fb(a0l), fb(a1l), fb(a2l), fb(a3l), b0h, b1h);
                }
            }
        }
    }

    // ---- Normalize and write O ----
    if (out_o) {
        float inv0 = 1.0f / l0, inv1 = 1.0f / l1;
        float* op = out_o + (bh * SS + (size_t)rb * BM) * DD;
        #pragma unroll
        for (int j = 0; j < 8; ++j) {
            int dc = 8 * j + 2 * t;
            *(float2*)(op + (size_t)row_l0 * DD + dc) =
                make_float2(oacc[j][0] * inv0, oacc[j][1] * inv0);
            *(float2*)(op + (size_t)row_l1 * DD + dc) =
                make_float2(oacc[j][2] * inv1, oacc[j][3] * inv1);
        }
    }
}

extern "C" void kernel_launch(void* const* d_in, const int* in_sizes, int n_in,
                              void* d_out, int out_size)
{
    const float* q    = (const float*)d_in[0];
    const float* k    = (const float*)d_in[1];
    const float* v    = (const float*)d_in[2];
    const int*   mask = (const int*)  d_in[3];

    const long long OUT_O_N = (long long)BB * HH * SS * DD;   // 8388608
    const long long OUT_S_N = (long long)BB * HH * SS * SS;   // 268435456

    float* o_ptr = 0;
    float* s_ptr = 0;
    if ((long long)out_size == OUT_O_N + OUT_S_N) {
        o_ptr = (float*)d_out;
        s_ptr = (float*)d_out + OUT_O_N;
    } else if ((long long)out_size == OUT_O_N) {
        o_ptr = (float*)d_out;
    } else if ((long long)out_size == OUT_S_N) {
        s_ptr = (float*)d_out;
    } else {
        o_ptr = (float*)d_out;   // fallback: at least produce the primary output
    }

    const int smem_bytes = SMEM_FLOATS * (int)sizeof(float);  // 96,256 B
    cudaFuncSetAttribute(attn_mma_kernel,
                         cudaFuncAttributeMaxDynamicSharedMemorySize, smem_bytes);

    dim3 grid(SS / BM, HH, BB);   // (16, 16, 4) = 1024 CTAs
    dim3 block(256);
    attn_mma_kernel<<<grid, block, smem_bytes>>>(q, k, v, mask, o_ptr, s_ptr);
}

// round 10
// speedup vs baseline: 1.3879x; 1.3064x over previous
#include <cuda_runtime.h>
#include <math_constants.h>
#include <cstdint>

// Problem shape (fixed by the dataset)
#define BB 4
#define HH 16
#define SS 2048
#define DD 64

#define BM 128   // query rows per CTA (8 warps x 16 rows)
#define BN 32    // key/value columns per tile
#define SQ 72    // stride for 64-wide rows (mod 32 == 8 -> conflict-free frags)
#define SK 40    // stride for 32-wide rows (mod 32 == 8)

// Dynamic smem layout (floats):
#define QS_OFF 0                        // [BM][SQ] Q fp32 (row r, col d)    9216
#define KH_OFF (QS_OFF + BM*SQ)         // [DD][SK] K tf32-hi (row d, col s) 2560
#define VH_OFF (KH_OFF + DD*SK)         // [BN][SQ] V tf32-hi (row s, col d) 2304
#define PS_OFF (VH_OFF + BN*SQ)         // [BM][SK] P fp32 (row r, col s)    5120
#define SMEM_FLOATS (PS_OFF + BM*SK)    // 19200 floats = 76,800 B

__device__ __forceinline__ uint32_t tf32_rna(float x) {
    uint32_t u; asm("cvt.rna.tf32.f32 %0, %1;" : "=r"(u) : "f"(x)); return u;
}
__device__ __forceinline__ void split2(float x, float &h, float &l) {
    h = __uint_as_float(tf32_rna(x));
    l = __uint_as_float(tf32_rna(x - h));
}
__device__ __forceinline__ uint32_t fb(float x) { return __float_as_uint(x); }

__device__ __forceinline__ void mma8(float* c,
    uint32_t a0, uint32_t a1, uint32_t a2, uint32_t a3,
    uint32_t b0, uint32_t b1)
{
    asm volatile(
        "mma.sync.aligned.m16n8k8.row.col.f32.tf32.tf32.f32 "
        "{%0,%1,%2,%3},{%4,%5,%6,%7},{%8,%9},{%0,%1,%2,%3};"
        : "+f"(c[0]), "+f"(c[1]), "+f"(c[2]), "+f"(c[3])
        : "r"(a0), "r"(a1), "r"(a2), "r"(a3), "r"(b0), "r"(b1));
}

__global__ __launch_bounds__(256, 2)
void attn_mma_kernel(const float* __restrict__ q,
                     const float* __restrict__ k,
                     const float* __restrict__ v,
                     const int*   __restrict__ mask,
                     float* __restrict__ out_o,   // may be null
                     float* __restrict__ out_s)   // may be null
{
    extern __shared__ float sm[];
    float* qs = sm + QS_OFF;
    float* kh = sm + KH_OFF;
    float* vh = sm + VH_OFF;
    float* ps = sm + PS_OFF;

    const int tid  = threadIdx.x;
    const int lane = tid & 31;
    const int w    = tid >> 5;       // warp 0..7 -> rows 16w..16w+15
    const int g    = lane >> 2;      // group 0..7
    const int t    = lane & 3;       // thread-in-group 0..3

    const int rb = blockIdx.x;
    const int h  = blockIdx.y;
    const int b  = blockIdx.z;

    const size_t bh = (size_t)b * HH + h;
    const float* qp = q + (bh * SS + (size_t)rb * BM) * DD;   // [BM][DD]
    const float* kp = k + bh * (size_t)DD * SS;               // [DD][SS]
    const float* vp = v + bh * (size_t)SS * DD;               // [SS][DD]
    const int*   mp = mask + ((size_t)b * SS + (size_t)rb * BM) * SS;  // [BM][SS]
    float* osp = out_s ? (out_s + (bh * SS + (size_t)rb * BM) * SS) : (float*)0;

    // ---- Load Q tile (128 rows x 16 float4 = 2048 float4s), fp32, once ----
    #pragma unroll
    for (int it = 0; it < 8; ++it) {
        int id4 = tid + it * 256;
        int r  = id4 >> 4;
        int d4 = (id4 & 15) * 4;
        *(float4*)(qs + r * SQ + d4) = *(const float4*)(qp + (size_t)r * DD + d4);
    }

    const int row_l0 = 16 * w + g;
    const int row_l1 = row_l0 + 8;
    const int* mrow0 = mp + (size_t)row_l0 * SS;
    const int* mrow1 = mp + (size_t)row_l1 * SS;

    float oacc[8][4];
    float m0 = -CUDART_INF_F, m1 = -CUDART_INF_F, l0 = 0.f, l1 = 0.f;
    #pragma unroll
    for (int j = 0; j < 8; ++j)
        oacc[j][0] = oacc[j][1] = oacc[j][2] = oacc[j][3] = 0.f;

    for (int jt = 0; jt < SS / BN; ++jt) {
        const int s0 = jt * BN;

        // Prefetch this tile's mask rows (one 128B line = full BN row)
        if (t == 0) {
            asm volatile("prefetch.global.L1 [%0];" :: "l"(mrow0 + s0));
            asm volatile("prefetch.global.L1 [%0];" :: "l"(mrow1 + s0));
        }

        __syncthreads();   // previous tile's consumers done before overwrite
        // ---- Load K tile [64 d][32 s], tf32-hi plane only ----
        #pragma unroll
        for (int it = 0; it < 2; ++it) {
            int id4 = tid + it * 256;
            int r  = id4 >> 3;             // 0..63 (d)
            int c4 = (id4 & 7) * 4;        // 0..28 (s)
            float4 kv = *(const float4*)(kp + (size_t)r * SS + s0 + c4);
            float4 hv;
            hv.x = __uint_as_float(tf32_rna(kv.x));
            hv.y = __uint_as_float(tf32_rna(kv.y));
            hv.z = __uint_as_float(tf32_rna(kv.z));
            hv.w = __uint_as_float(tf32_rna(kv.w));
            *(float4*)(kh + r * SK + c4) = hv;
        }
        // ---- Load V tile [32 s][64 d], tf32-hi plane only ----
        #pragma unroll
        for (int it = 0; it < 2; ++it) {
            int id4 = tid + it * 256;
            int r  = id4 >> 4;             // 0..31 (s)
            int c4 = (id4 & 15) * 4;       // 0..60 (d)
            float4 vv = *(const float4*)(vp + (size_t)(s0 + r) * DD + c4);
            float4 hv;
            hv.x = __uint_as_float(tf32_rna(vv.x));
            hv.y = __uint_as_float(tf32_rna(vv.y));
            hv.z = __uint_as_float(tf32_rna(vv.z));
            hv.w = __uint_as_float(tf32_rna(vv.w));
            *(float4*)(vh + r * SQ + c4) = hv;
        }
        __syncthreads();

        // ---- S = Q K : 16x32 per warp, split-A 2xTF32 ----
        float sacc[4][4];
        #pragma unroll
        for (int j = 0; j < 4; ++j)
            sacc[j][0] = sacc[j][1] = sacc[j][2] = sacc[j][3] = 0.f;

        {
            const float* q0 = qs + row_l0 * SQ;
            const float* q1 = qs + row_l1 * SQ;
            #pragma unroll 1
            for (int k0 = 0; k0 < DD; k0 += 8) {
                float a0h, a0l, a1h, a1l, a2h, a2l, a3h, a3l;
                split2(q0[k0 + t],     a0h, a0l);
                split2(q1[k0 + t],     a1h, a1l);
                split2(q0[k0 + t + 4], a2h, a2l);
                split2(q1[k0 + t + 4], a3h, a3l);
                const float* kbh  = kh + (k0 + t) * SK + g;
                const float* kbh4 = kh + (k0 + t + 4) * SK + g;
                #pragma unroll
                for (int j = 0; j < 4; ++j) {
                    uint32_t b0h = fb(kbh[8 * j]), b1h = fb(kbh4[8 * j]);
                    mma8(sacc[j], fb(a0h), fb(a1h), fb(a2h), fb(a3h), b0h, b1h);
                    mma8(sacc[j], fb(a0l), fb(a1l), fb(a2l), fb(a3l), b0h, b1h);
                }
            }
        }

        // ---- Mask, scale, store scores (streaming), online softmax ----
        float rmax0 = -CUDART_INF_F, rmax1 = -CUDART_INF_F;
        #pragma unroll
        for (int j = 0; j < 4; ++j) {
            const int coff = s0 + 2 * t + 8 * j;
            int2 mr0 = *(const int2*)(mrow0 + coff);
            int2 mr1 = *(const int2*)(mrow1 + coff);
            float s00 = (mr0.x == 0) ? -1e10f : sacc[j][0] * 0.125f;
            float s01 = (mr0.y == 0) ? -1e10f : sacc[j][1] * 0.125f;
            float s10 = (mr1.x == 0) ? -1e10f : sacc[j][2] * 0.125f;
            float s11 = (mr1.y == 0) ? -1e10f : sacc[j][3] * 0.125f;
            if (osp) {
                __stcs((float2*)(osp + (size_t)row_l0 * SS + coff), make_float2(s00, s01));
                __stcs((float2*)(osp + (size_t)row_l1 * SS + coff), make_float2(s10, s11));
            }
            sacc[j][0] = s00; sacc[j][1] = s01; sacc[j][2] = s10; sacc[j][3] = s11;
            rmax0 = fmaxf(rmax0, fmaxf(s00, s01));
            rmax1 = fmaxf(rmax1, fmaxf(s10, s11));
        }
        rmax0 = fmaxf(rmax0, __shfl_xor_sync(0xffffffffu, rmax0, 1));
        rmax0 = fmaxf(rmax0, __shfl_xor_sync(0xffffffffu, rmax0, 2));
        rmax1 = fmaxf(rmax1, __shfl_xor_sync(0xffffffffu, rmax1, 1));
        rmax1 = fmaxf(rmax1, __shfl_xor_sync(0xffffffffu, rmax1, 2));

        float mn0 = fmaxf(m0, rmax0), mn1 = fmaxf(m1, rmax1);
        float corr0 = __expf(m0 - mn0), corr1 = __expf(m1 - mn1);
        m0 = mn0; m1 = mn1;

        float rs0 = 0.f, rs1 = 0.f;
        float* p0 = ps + row_l0 * SK + 2 * t;
        float* p1 = ps + row_l1 * SK + 2 * t;
        #pragma unroll
        for (int j = 0; j < 4; ++j) {
            float p00 = __expf(sacc[j][0] - mn0);
            float p01 = __expf(sacc[j][1] - mn0);
            float p10 = __expf(sacc[j][2] - mn1);
            float p11 = __expf(sacc[j][3] - mn1);
            rs0 += p00 + p01; rs1 += p10 + p11;
            *(float2*)(p0 + 8 * j) = make_float2(p00, p01);
            *(float2*)(p1 + 8 * j) = make_float2(p10, p11);
        }
        rs0 += __shfl_xor_sync(0xffffffffu, rs0, 1);
        rs0 += __shfl_xor_sync(0xffffffffu, rs0, 2);
        rs1 += __shfl_xor_sync(0xffffffffu, rs1, 1);
        rs1 += __shfl_xor_sync(0xffffffffu, rs1, 2);
        l0 = l0 * corr0 + rs0;
        l1 = l1 * corr1 + rs1;
        #pragma unroll
        for (int j = 0; j < 8; ++j) {
            oacc[j][0] *= corr0; oacc[j][1] *= corr0;
            oacc[j][2] *= corr1; oacc[j][3] *= corr1;
        }
        __syncwarp();   // ps rows warp-private: order STS -> LDS within warp

        // ---- O += P V : 16x64 per warp, split-A 2xTF32 ----
        {
            const float* pr0 = ps + row_l0 * SK;
            const float* pr1 = ps + row_l1 * SK;
            #pragma unroll 1
            for (int k0 = 0; k0 < BN; k0 += 8) {
                float a0h, a0l, a1h, a1l, a2h, a2l, a3h, a3l;
                split2(pr0[k0 + t],     a0h, a0l);
                split2(pr1[k0 + t],     a1h, a1l);
                split2(pr0[k0 + t + 4], a2h, a2l);
                split2(pr1[k0 + t + 4], a3h, a3l);
                const float* vbh  = vh + (k0 + t) * SQ + g;
                const float* vbh4 = vh + (k0 + t + 4) * SQ + g;
                #pragma unroll
                for (int j = 0; j < 8; ++j) {
                    uint32_t b0h = fb(vbh[8 * j]), b1h = fb(vbh4[8 * j]);
                    mma8(oacc[j], fb(a0h), fb(a1h), fb(a2h), fb(a3h), b0h, b1h);
                    mma8(oacc[j], fb(a0l), fb(a1l), fb(a2l), fb(a3l), b0h, b1h);
                }
            }
        }
    }

    // ---- Normalize and write O ----
    if (out_o) {
        float inv0 = 1.0f / l0, inv1 = 1.0f / l1;
        float* op = out_o + (bh * SS + (size_t)rb * BM) * DD;
        #pragma unroll
        for (int j = 0; j < 8; ++j) {
            int dc = 8 * j + 2 * t;
            *(float2*)(op + (size_t)row_l0 * DD + dc) =
                make_float2(oacc[j][0] * inv0, oacc[j][1] * inv0);
            *(float2*)(op + (size_t)row_l1 * DD + dc) =
                make_float2(oacc[j][2] * inv1, oacc[j][3] * inv1);
        }
    }
}

extern "C" void kernel_launch(void* const* d_in, const int* in_sizes, int n_in,
                              void* d_out, int out_size)
{
    const float* q    = (const float*)d_in[0];
    const float* k    = (const float*)d_in[1];
    const float* v    = (const float*)d_in[2];
    const int*   mask = (const int*)  d_in[3];

    const long long OUT_O_N = (long long)BB * HH * SS * DD;   // 8388608
    const long long OUT_S_N = (long long)BB * HH * SS * SS;   // 268435456

    float* o_ptr = 0;
    float* s_ptr = 0;
    if ((long long)out_size == OUT_O_N + OUT_S_N) {
        o_ptr = (float*)d_out;
        s_ptr = (float*)d_out + OUT_O_N;
    } else if ((long long)out_size == OUT_O_N) {
        o_ptr = (float*)d_out;
    } else if ((long long)out_size == OUT_S_N) {
        s_ptr = (float*)d_out;
    } else {
        o_ptr = (float*)d_out;   // fallback: at least produce the primary output
    }

    const int smem_bytes = SMEM_FLOATS * (int)sizeof(float);  // 76,800 B
    cudaFuncSetAttribute(attn_mma_kernel,
                         cudaFuncAttributeMaxDynamicSharedMemorySize, smem_bytes);

    dim3 grid(SS / BM, HH, BB);   // (16, 16, 4) = 1024 CTAs
    dim3 block(256);
    attn_mma_kernel<<<grid, block, smem_bytes>>>(q, k, v, mask, o_ptr, s_ptr);
}

// round 12
// speedup vs baseline: 1.4852x; 1.0701x over previous
#include <cuda_runtime.h>
#include <math_constants.h>
#include <cstdint>

// Problem shape (fixed by the dataset)
#define BB 4
#define HH 16
#define SS 2048
#define DD 64

#define BM 128   // query rows per CTA (8 warps x 16 rows)
#define BN 64    // key/value columns per tile
#define SA 68    // stride for A-operand tiles (Q,P): mod 32 == 4 -> banks 4g+t conflict-free
#define SB 72    // stride for B-operand tiles (K,V): mod 32 == 8 -> banks 8t+g conflict-free

// Dynamic smem layout (floats):
#define QS_OFF 0                        // [BM][SA] Q fp32 (row r, col d)     8704
#define KH_OFF (QS_OFF + BM*SA)         // [DD][SB] K tf32-hi (row d, col s)  4608
#define VH_OFF (KH_OFF + DD*SB)         // [BN][SB] V tf32-hi (row s, col d)  4608
#define PS_OFF (VH_OFF + BN*SB)         // [BM][SA] P fp32 (row r, col s)     8704
#define SMEM_FLOATS (PS_OFF + BM*SA)    // 26624 floats = 106,496 B

__device__ __forceinline__ uint32_t tf32_rna(float x) {
    uint32_t u; asm("cvt.rna.tf32.f32 %0, %1;" : "=r"(u) : "f"(x)); return u;
}
__device__ __forceinline__ void split2(float x, float &h, float &l) {
    h = __uint_as_float(tf32_rna(x));
    l = __uint_as_float(tf32_rna(x - h));
}
__device__ __forceinline__ uint32_t fb(float x) { return __float_as_uint(x); }

__device__ __forceinline__ void mma8(float* c,
    uint32_t a0, uint32_t a1, uint32_t a2, uint32_t a3,
    uint32_t b0, uint32_t b1)
{
    asm volatile(
        "mma.sync.aligned.m16n8k8.row.col.f32.tf32.tf32.f32 "
        "{%0,%1,%2,%3},{%4,%5,%6,%7},{%8,%9},{%0,%1,%2,%3};"
        : "+f"(c[0]), "+f"(c[1]), "+f"(c[2]), "+f"(c[3])
        : "r"(a0), "r"(a1), "r"(a2), "r"(a3), "r"(b0), "r"(b1));
}

__global__ __launch_bounds__(256, 2)
void attn_mma_kernel(const float* __restrict__ q,
                     const float* __restrict__ k,
                     const float* __restrict__ v,
                     const int*   __restrict__ mask,
                     float* __restrict__ out_o,   // may be null
                     float* __restrict__ out_s)   // may be null
{
    extern __shared__ float sm[];
    float* qs = sm + QS_OFF;
    float* kh = sm + KH_OFF;
    float* vh = sm + VH_OFF;
    float* ps = sm + PS_OFF;

    const int tid  = threadIdx.x;
    const int lane = tid & 31;
    const int w    = tid >> 5;       // warp 0..7 -> rows 16w..16w+15
    const int g    = lane >> 2;      // group 0..7
    const int t    = lane & 3;       // thread-in-group 0..3

    const int rb = blockIdx.x;
    const int h  = blockIdx.y;
    const int b  = blockIdx.z;

    const size_t bh = (size_t)b * HH + h;
    const float* qp = q + (bh * SS + (size_t)rb * BM) * DD;   // [BM][DD]
    const float* kp = k + bh * (size_t)DD * SS;               // [DD][SS]
    const float* vp = v + bh * (size_t)SS * DD;               // [SS][DD]
    const int*   mp = mask + ((size_t)b * SS + (size_t)rb * BM) * SS;  // [BM][SS]
    float* osp = out_s ? (out_s + (bh * SS + (size_t)rb * BM) * SS) : (float*)0;

    // ---- Load Q tile (128 rows x 16 float4 = 2048 float4s), fp32, once ----
    #pragma unroll
    for (int it = 0; it < 8; ++it) {
        int id4 = tid + it * 256;
        int r  = id4 >> 4;
        int d4 = (id4 & 15) * 4;
        *(float4*)(qs + r * SA + d4) = *(const float4*)(qp + (size_t)r * DD + d4);
    }

    const int row_l0 = 16 * w + g;
    const int row_l1 = row_l0 + 8;
    const int* mrow0 = mp + (size_t)row_l0 * SS;
    const int* mrow1 = mp + (size_t)row_l1 * SS;

    float oacc[8][4];
    float m0 = -CUDART_INF_F, m1 = -CUDART_INF_F, l0 = 0.f, l1 = 0.f;
    #pragma unroll
    for (int j = 0; j < 8; ++j)
        oacc[j][0] = oacc[j][1] = oacc[j][2] = oacc[j][3] = 0.f;

    for (int jt = 0; jt < SS / BN; ++jt) {
        const int s0 = jt * BN;

        // Prefetch this tile's mask rows (two 128B lines cover the BN=64 row)
        if (t == 0) {
            asm volatile("prefetch.global.L1 [%0];" :: "l"(mrow0 + s0));
            asm volatile("prefetch.global.L1 [%0];" :: "l"(mrow0 + s0 + 32));
            asm volatile("prefetch.global.L1 [%0];" :: "l"(mrow1 + s0));
            asm volatile("prefetch.global.L1 [%0];" :: "l"(mrow1 + s0 + 32));
        }

        __syncthreads();   // previous tile's consumers done before overwrite
        // ---- Load K tile [64 d][64 s], tf32-hi plane only ----
        #pragma unroll
        for (int it = 0; it < 4; ++it) {
            int id4 = tid + it * 256;
            int r  = id4 >> 4;             // 0..63 (d)
            int c4 = (id4 & 15) * 4;       // 0..60 (s)
            float4 kv = *(const float4*)(kp + (size_t)r * SS + s0 + c4);
            float4 hv;
            hv.x = __uint_as_float(tf32_rna(kv.x));
            hv.y = __uint_as_float(tf32_rna(kv.y));
            hv.z = __uint_as_float(tf32_rna(kv.z));
            hv.w = __uint_as_float(tf32_rna(kv.w));
            *(float4*)(kh + r * SB + c4) = hv;
        }
        // ---- Load V tile [64 s][64 d], tf32-hi plane only ----
        #pragma unroll
        for (int it = 0; it < 4; ++it) {
            int id4 = tid + it * 256;
            int r  = id4 >> 4;             // 0..63 (s)
            int c4 = (id4 & 15) * 4;       // 0..60 (d)
            float4 vv = *(const float4*)(vp + (size_t)(s0 + r) * DD + c4);
            float4 hv;
            hv.x = __uint_as_float(tf32_rna(vv.x));
            hv.y = __uint_as_float(tf32_rna(vv.y));
            hv.z = __uint_as_float(tf32_rna(vv.z));
            hv.w = __uint_as_float(tf32_rna(vv.w));
            *(float4*)(vh + r * SB + c4) = hv;
        }
        __syncthreads();

        // ---- S = Q K : 16x64 per warp, split-A 2xTF32 ----
        float sacc[8][4];
        #pragma unroll
        for (int j = 0; j < 8; ++j)
            sacc[j][0] = sacc[j][1] = sacc[j][2] = sacc[j][3] = 0.f;

        {
            const float* q0 = qs + row_l0 * SA;
            const float* q1 = qs + row_l1 * SA;
            #pragma unroll 1
            for (int k0 = 0; k0 < DD; k0 += 8) {
                float a0h, a0l, a1h, a1l, a2h, a2l, a3h, a3l;
                split2(q0[k0 + t],     a0h, a0l);
                split2(q1[k0 + t],     a1h, a1l);
                split2(q0[k0 + t + 4], a2h, a2l);
                split2(q1[k0 + t + 4], a3h, a3l);
                const float* kbh  = kh + (k0 + t) * SB + g;
                const float* kbh4 = kh + (k0 + t + 4) * SB + g;
                #pragma unroll
                for (int j = 0; j < 8; ++j) {
                    uint32_t b0h = fb(kbh[8 * j]), b1h = fb(kbh4[8 * j]);
                    mma8(sacc[j], fb(a0h), fb(a1h), fb(a2h), fb(a3h), b0h, b1h);
                    mma8(sacc[j], fb(a0l), fb(a1l), fb(a2l), fb(a3l), b0h, b1h);
                }
            }
        }

        // ---- Mask, scale, store scores (streaming), online softmax ----
        float rmax0 = -CUDART_INF_F, rmax1 = -CUDART_INF_F;
        #pragma unroll
        for (int j = 0; j < 8; ++j) {
            const int coff = s0 + 2 * t + 8 * j;
            int2 mr0 = *(const int2*)(mrow0 + coff);
            int2 mr1 = *(const int2*)(mrow1 + coff);
            float s00 = (mr0.x == 0) ? -1e10f : sacc[j][0] * 0.125f;
            float s01 = (mr0.y == 0) ? -1e10f : sacc[j][1] * 0.125f;
            float s10 = (mr1.x == 0) ? -1e10f : sacc[j][2] * 0.125f;
            float s11 = (mr1.y == 0) ? -1e10f : sacc[j][3] * 0.125f;
            if (osp) {
                __stcs((float2*)(osp + (size_t)row_l0 * SS + coff), make_float2(s00, s01));
                __stcs((float2*)(osp + (size_t)row_l1 * SS + coff), make_float2(s10, s11));
            }
            sacc[j][0] = s00; sacc[j][1] = s01; sacc[j][2] = s10; sacc[j][3] = s11;
            rmax0 = fmaxf(rmax0, fmaxf(s00, s01));
            rmax1 = fmaxf(rmax1, fmaxf(s10, s11));
        }
        rmax0 = fmaxf(rmax0, __shfl_xor_sync(0xffffffffu, rmax0, 1));
        rmax0 = fmaxf(rmax0, __shfl_xor_sync(0xffffffffu, rmax0, 2));
        rmax1 = fmaxf(rmax1, __shfl_xor_sync(0xffffffffu, rmax1, 1));
        rmax1 = fmaxf(rmax1, __shfl_xor_sync(0xffffffffu, rmax1, 2));

        float mn0 = fmaxf(m0, rmax0), mn1 = fmaxf(m1, rmax1);
        float corr0 = __expf(m0 - mn0), corr1 = __expf(m1 - mn1);
        m0 = mn0; m1 = mn1;

        float rs0 = 0.f, rs1 = 0.f;
        float* p0 = ps + row_l0 * SA + 2 * t;
        float* p1 = ps + row_l1 * SA + 2 * t;
        #pragma unroll
        for (int j = 0; j < 8; ++j) {
            float p00 = __expf(sacc[j][0] - mn0);
            float p01 = __expf(sacc[j][1] - mn0);
            float p10 = __expf(sacc[j][2] - mn1);
            float p11 = __expf(sacc[j][3] - mn1);
            rs0 += p00 + p01; rs1 += p10 + p11;
            *(float2*)(p0 + 8 * j) = make_float2(p00, p01);
            *(float2*)(p1 + 8 * j) = make_float2(p10, p11);
        }
        rs0 += __shfl_xor_sync(0xffffffffu, rs0, 1);
        rs0 += __shfl_xor_sync(0xffffffffu, rs0, 2);
        rs1 += __shfl_xor_sync(0xffffffffu, rs1, 1);
        rs1 += __shfl_xor_sync(0xffffffffu, rs1, 2);
        l0 = l0 * corr0 + rs0;
        l1 = l1 * corr1 + rs1;
        #pragma unroll
        for (int j = 0; j < 8; ++j) {
            oacc[j][0] *= corr0; oacc[j][1] *= corr0;
            oacc[j][2] *= corr1; oacc[j][3] *= corr1;
        }
        __syncwarp();   // ps rows warp-private: order STS -> LDS within warp

        // ---- O += P V : 16x64 per warp, split-A 2xTF32 ----
        {
            const float* pr0 = ps + row_l0 * SA;
            const float* pr1 = ps + row_l1 * SA;
            #pragma unroll 1
            for (int k0 = 0; k0 < BN; k0 += 8) {
                float a0h, a0l, a1h, a1l, a2h, a2l, a3h, a3l;
                split2(pr0[k0 + t],     a0h, a0l);
                split2(pr1[k0 + t],     a1h, a1l);
                split2(pr0[k0 + t + 4], a2h, a2l);
                split2(pr1[k0 + t + 4], a3h, a3l);
                const float* vbh  = vh + (k0 + t) * SB + g;
                const float* vbh4 = vh + (k0 + t + 4) * SB + g;
                #pragma unroll
                for (int j = 0; j < 8; ++j) {
                    uint32_t b0h = fb(vbh[8 * j]), b1h = fb(vbh4[8 * j]);
                    mma8(oacc[j], fb(a0h), fb(a1h), fb(a2h), fb(a3h), b0h, b1h);
                    mma8(oacc[j], fb(a0l), fb(a1l), fb(a2l), fb(a3l), b0h, b1h);
                }
            }
        }
    }

    // ---- Normalize and write O ----
    if (out_o) {
        float inv0 = 1.0f / l0, inv1 = 1.0f / l1;
        float* op = out_o + (bh * SS + (size_t)rb * BM) * DD;
        #pragma unroll
        for (int j = 0; j < 8; ++j) {
            int dc = 8 * j + 2 * t;
            *(float2*)(op + (size_t)row_l0 * DD + dc) =
                make_float2(oacc[j][0] * inv0, oacc[j][1] * inv0);
            *(float2*)(op + (size_t)row_l1 * DD + dc) =
                make_float2(oacc[j][2] * inv1, oacc[j][3] * inv1);
        }
    }
}

extern "C" void kernel_launch(void* const* d_in, const int* in_sizes, int n_in,
                              void* d_out, int out_size)
{
    const float* q    = (const float*)d_in[0];
    const float* k    = (const float*)d_in[1];
    const float* v    = (const float*)d_in[2];
    const int*   mask = (const int*)  d_in[3];

    const long long OUT_O_N = (long long)BB * HH * SS * DD;   // 8388608
    const long long OUT_S_N = (long long)BB * HH * SS * SS;   // 268435456

    float* o_ptr = 0;
    float* s_ptr = 0;
    if ((long long)out_size == OUT_O_N + OUT_S_N) {
        o_ptr = (float*)d_out;
        s_ptr = (float*)d_out + OUT_O_N;
    } else if ((long long)out_size == OUT_O_N) {
        o_ptr = (float*)d_out;
    } else if ((long long)out_size == OUT_S_N) {
        s_ptr = (float*)d_out;
    } else {
        o_ptr = (float*)d_out;   // fallback: at least produce the primary output
    }

    const int smem_bytes = SMEM_FLOATS * (int)sizeof(float);  // 106,496 B
    cudaFuncSetAttribute(attn_mma_kernel,
                         cudaFuncAttributeMaxDynamicSharedMemorySize, smem_bytes);

    dim3 grid(SS / BM, HH, BB);   // (16, 16, 4) = 1024 CTAs
    dim3 block(256);
    attn_mma_kernel<<<grid, block, smem_bytes>>>(q, k, v, mask, o_ptr, s_ptr);
}

// round 14
// speedup vs baseline: 1.6653x; 1.1212x over previous
#include <cuda_runtime.h>
#include <math_constants.h>
#include <cstdint>

// Problem shape (fixed by the dataset)
#define BB 4
#define HH 16
#define SS 2048
#define DD 64

#define BM 128   // query rows per CTA (8 warps x 16 rows)
#define BN 64    // key/value columns per tile
#define SA 68    // stride for A-operand tiles (Q,P): mod 32 == 4 -> banks 4g+t conflict-free
#define SB 72    // stride for B-operand tiles (K,V): mod 32 == 8 -> banks 8t+g conflict-free

// Dynamic smem layout (floats):
#define QS_OFF 0                        // [BM][SA] Q/8 fp32 (row r, col d)   8704
#define KH_OFF (QS_OFF + BM*SA)         // [DD][SB] K tf32-hi (row d, col s)  4608
#define VH_OFF (KH_OFF + DD*SB)         // [BN][SB] V tf32-hi (row s, col d)  4608
#define PS_OFF (VH_OFF + BN*SB)         // [BM][SA] P tf32 (row r, col s)     8704
#define SMEM_FLOATS (PS_OFF + BM*SA)    // 26624 floats = 106,496 B

__device__ __forceinline__ uint32_t tf32_rna(float x) {
    uint32_t u; asm("cvt.rna.tf32.f32 %0, %1;" : "=r"(u) : "f"(x)); return u;
}
__device__ __forceinline__ void split2(float x, float &h, float &l) {
    h = __uint_as_float(tf32_rna(x));
    l = __uint_as_float(tf32_rna(x - h));
}
__device__ __forceinline__ uint32_t fb(float x) { return __float_as_uint(x); }

__device__ __forceinline__ void mma8(float* c,
    uint32_t a0, uint32_t a1, uint32_t a2, uint32_t a3,
    uint32_t b0, uint32_t b1)
{
    asm volatile(
        "mma.sync.aligned.m16n8k8.row.col.f32.tf32.tf32.f32 "
        "{%0,%1,%2,%3},{%4,%5,%6,%7},{%8,%9},{%0,%1,%2,%3};"
        : "+f"(c[0]), "+f"(c[1]), "+f"(c[2]), "+f"(c[3])
        : "r"(a0), "r"(a1), "r"(a2), "r"(a3), "r"(b0), "r"(b1));
}

__global__ __launch_bounds__(256, 2)
void attn_mma_kernel(const float* __restrict__ q,
                     const float* __restrict__ k,
                     const float* __restrict__ v,
                     const int*   __restrict__ mask,
                     float* __restrict__ out_o,   // may be null
                     float* __restrict__ out_s)   // may be null
{
    extern __shared__ float sm[];
    float* qs = sm + QS_OFF;
    float* kh = sm + KH_OFF;
    float* vh = sm + VH_OFF;
    float* ps = sm + PS_OFF;

    const int tid  = threadIdx.x;
    const int lane = tid & 31;
    const int w    = tid >> 5;       // warp 0..7 -> rows 16w..16w+15
    const int g    = lane >> 2;      // group 0..7
    const int t    = lane & 3;       // thread-in-group 0..3

    const int rb = blockIdx.x;
    const int h  = blockIdx.y;
    const int b  = blockIdx.z;

    const size_t bh = (size_t)b * HH + h;
    const float* qp = q + (bh * SS + (size_t)rb * BM) * DD;   // [BM][DD]
    const float* kp = k + bh * (size_t)DD * SS;               // [DD][SS]
    const float* vp = v + bh * (size_t)SS * DD;               // [SS][DD]
    const int*   mp = mask + ((size_t)b * SS + (size_t)rb * BM) * SS;  // [BM][SS]
    float* osp = out_s ? (out_s + (bh * SS + (size_t)rb * BM) * SS) : (float*)0;

    // ---- Load Q tile (128 rows x 64 d) scaled by 1/8 (exact pow2), once ----
    #pragma unroll
    for (int it = 0; it < 8; ++it) {
        int id4 = tid + it * 256;
        int r  = id4 >> 4;
        int d4 = (id4 & 15) * 4;
        float4 qv = *(const float4*)(qp + (size_t)r * DD + d4);
        qv.x *= 0.125f; qv.y *= 0.125f; qv.z *= 0.125f; qv.w *= 0.125f;
        *(float4*)(qs + r * SA + d4) = qv;
    }

    const int row_l0 = 16 * w + g;
    const int row_l1 = row_l0 + 8;
    const int* mrow0 = mp + (size_t)row_l0 * SS;
    const int* mrow1 = mp + (size_t)row_l1 * SS;

    float oacc[8][4];
    float m0 = -CUDART_INF_F, m1 = -CUDART_INF_F, l0 = 0.f, l1 = 0.f;
    #pragma unroll
    for (int j = 0; j < 8; ++j)
        oacc[j][0] = oacc[j][1] = oacc[j][2] = oacc[j][3] = 0.f;

    for (int jt = 0; jt < SS / BN; ++jt) {
        const int s0 = jt * BN;

        // Prefetch this tile's mask rows (two 128B lines cover the BN=64 row)
        if (t == 0) {
            asm volatile("prefetch.global.L1 [%0];" :: "l"(mrow0 + s0));
            asm volatile("prefetch.global.L1 [%0];" :: "l"(mrow0 + s0 + 32));
            asm volatile("prefetch.global.L1 [%0];" :: "l"(mrow1 + s0));
            asm volatile("prefetch.global.L1 [%0];" :: "l"(mrow1 + s0 + 32));
        }

        __syncthreads();   // previous tile's consumers done before overwrite
        // ---- Load K tile [64 d][64 s], tf32-hi plane only ----
        #pragma unroll
        for (int it = 0; it < 4; ++it) {
            int id4 = tid + it * 256;
            int r  = id4 >> 4;             // 0..63 (d)
            int c4 = (id4 & 15) * 4;       // 0..60 (s)
            float4 kv = *(const float4*)(kp + (size_t)r * SS + s0 + c4);
            float4 hv;
            hv.x = __uint_as_float(tf32_rna(kv.x));
            hv.y = __uint_as_float(tf32_rna(kv.y));
            hv.z = __uint_as_float(tf32_rna(kv.z));
            hv.w = __uint_as_float(tf32_rna(kv.w));
            *(float4*)(kh + r * SB + c4) = hv;
        }
        // ---- Load V tile [64 s][64 d], tf32-hi plane only ----
        #pragma unroll
        for (int it = 0; it < 4; ++it) {
            int id4 = tid + it * 256;
            int r  = id4 >> 4;             // 0..63 (s)
            int c4 = (id4 & 15) * 4;       // 0..60 (d)
            float4 vv = *(const float4*)(vp + (size_t)(s0 + r) * DD + c4);
            float4 hv;
            hv.x = __uint_as_float(tf32_rna(vv.x));
            hv.y = __uint_as_float(tf32_rna(vv.y));
            hv.z = __uint_as_float(tf32_rna(vv.z));
            hv.w = __uint_as_float(tf32_rna(vv.w));
            *(float4*)(vh + r * SB + c4) = hv;
        }
        __syncthreads();

        // ---- S = (Q/8) K : 16x64 per warp, split-A 2xTF32 ----
        float sacc[8][4];
        #pragma unroll
        for (int j = 0; j < 8; ++j)
            sacc[j][0] = sacc[j][1] = sacc[j][2] = sacc[j][3] = 0.f;

        {
            const float* q0 = qs + row_l0 * SA;
            const float* q1 = qs + row_l1 * SA;
            #pragma unroll 1
            for (int k0 = 0; k0 < DD; k0 += 8) {
                float a0h, a0l, a1h, a1l, a2h, a2l, a3h, a3l;
                split2(q0[k0 + t],     a0h, a0l);
                split2(q1[k0 + t],     a1h, a1l);
                split2(q0[k0 + t + 4], a2h, a2l);
                split2(q1[k0 + t + 4], a3h, a3l);
                const float* kbh  = kh + (k0 + t) * SB + g;
                const float* kbh4 = kh + (k0 + t + 4) * SB + g;
                #pragma unroll
                for (int j = 0; j < 8; ++j) {
                    uint32_t b0h = fb(kbh[8 * j]), b1h = fb(kbh4[8 * j]);
                    mma8(sacc[j], fb(a0h), fb(a1h), fb(a2h), fb(a3h), b0h, b1h);
                    mma8(sacc[j], fb(a0l), fb(a1l), fb(a2l), fb(a3l), b0h, b1h);
                }
            }
        }

        // ---- Mask, store scores (streaming), online softmax ----
        float rmax0 = -CUDART_INF_F, rmax1 = -CUDART_INF_F;
        #pragma unroll
        for (int j = 0; j < 8; ++j) {
            const int coff = s0 + 2 * t + 8 * j;
            int2 mr0 = *(const int2*)(mrow0 + coff);
            int2 mr1 = *(const int2*)(mrow1 + coff);
            float s00 = (mr0.x == 0) ? -1e10f : sacc[j][0];
            float s01 = (mr0.y == 0) ? -1e10f : sacc[j][1];
            float s10 = (mr1.x == 0) ? -1e10f : sacc[j][2];
            float s11 = (mr1.y == 0) ? -1e10f : sacc[j][3];
            if (osp) {
                __stcs((float2*)(osp + (size_t)row_l0 * SS + coff), make_float2(s00, s01));
                __stcs((float2*)(osp + (size_t)row_l1 * SS + coff), make_float2(s10, s11));
            }
            sacc[j][0] = s00; sacc[j][1] = s01; sacc[j][2] = s10; sacc[j][3] = s11;
            rmax0 = fmaxf(rmax0, fmaxf(s00, s01));
            rmax1 = fmaxf(rmax1, fmaxf(s10, s11));
        }
        rmax0 = fmaxf(rmax0, __shfl_xor_sync(0xffffffffu, rmax0, 1));
        rmax0 = fmaxf(rmax0, __shfl_xor_sync(0xffffffffu, rmax0, 2));
        rmax1 = fmaxf(rmax1, __shfl_xor_sync(0xffffffffu, rmax1, 1));
        rmax1 = fmaxf(rmax1, __shfl_xor_sync(0xffffffffu, rmax1, 2));

        float mn0 = fmaxf(m0, rmax0), mn1 = fmaxf(m1, rmax1);
        float corr0 = __expf(m0 - mn0), corr1 = __expf(m1 - mn1);
        m0 = mn0; m1 = mn1;

        // P rounded to tf32 once; rounded values used for BOTH numerator (PV)
        // and denominator (l) so normalization errors partially cancel.
        float rs0 = 0.f, rs1 = 0.f;
        float* p0 = ps + row_l0 * SA + 2 * t;
        float* p1 = ps + row_l1 * SA + 2 * t;
        #pragma unroll
        for (int j = 0; j < 8; ++j) {
            float p00 = __uint_as_float(tf32_rna(__expf(sacc[j][0] - mn0)));
            float p01 = __uint_as_float(tf32_rna(__expf(sacc[j][1] - mn0)));
            float p10 = __uint_as_float(tf32_rna(__expf(sacc[j][2] - mn1)));
            float p11 = __uint_as_float(tf32_rna(__expf(sacc[j][3] - mn1)));
            rs0 += p00 + p01; rs1 += p10 + p11;
            *(float2*)(p0 + 8 * j) = make_float2(p00, p01);
            *(float2*)(p1 + 8 * j) = make_float2(p10, p11);
        }
        rs0 += __shfl_xor_sync(0xffffffffu, rs0, 1);
        rs0 += __shfl_xor_sync(0xffffffffu, rs0, 2);
        rs1 += __shfl_xor_sync(0xffffffffu, rs1, 1);
        rs1 += __shfl_xor_sync(0xffffffffu, rs1, 2);
        l0 = l0 * corr0 + rs0;
        l1 = l1 * corr1 + rs1;
        #pragma unroll
        for (int j = 0; j < 8; ++j) {
            oacc[j][0] *= corr0; oacc[j][1] *= corr0;
            oacc[j][2] *= corr1; oacc[j][3] *= corr1;
        }
        __syncwarp();   // ps rows warp-private: order STS -> LDS within warp

        // ---- O += P V : 16x64 per warp, single-pass tf32 (P already tf32) ----
        {
            const float* pr0 = ps + row_l0 * SA;
            const float* pr1 = ps + row_l1 * SA;
            #pragma unroll 1
            for (int k0 = 0; k0 < BN; k0 += 8) {
                uint32_t a0 = fb(pr0[k0 + t]);
                uint32_t a1 = fb(pr1[k0 + t]);
                uint32_t a2 = fb(pr0[k0 + t + 4]);
                uint32_t a3 = fb(pr1[k0 + t + 4]);
                const float* vbh  = vh + (k0 + t) * SB + g;
                const float* vbh4 = vh + (k0 + t + 4) * SB + g;
                #pragma unroll
                for (int j = 0; j < 8; ++j) {
                    uint32_t b0h = fb(vbh[8 * j]), b1h = fb(vbh4[8 * j]);
                    mma8(oacc[j], a0, a1, a2, a3, b0h, b1h);
                }
            }
        }
    }

    // ---- Normalize and write O ----
    if (out_o) {
        float inv0 = 1.0f / l0, inv1 = 1.0f / l1;
        float* op = out_o + (bh * SS + (size_t)rb * BM) * DD;
        #pragma unroll
        for (int j = 0; j < 8; ++j) {
            int dc = 8 * j + 2 * t;
            *(float2*)(op + (size_t)row_l0 * DD + dc) =
                make_float2(oacc[j][0] * inv0, oacc[j][1] * inv0);
            *(float2*)(op + (size_t)row_l1 * DD + dc) =
                make_float2(oacc[j][2] * inv1, oacc[j][3] * inv1);
        }
    }
}

extern "C" void kernel_launch(void* const* d_in, const int* in_sizes, int n_in,
                              void* d_out, int out_size)
{
    const float* q    = (const float*)d_in[0];
    const float* k    = (const float*)d_in[1];
    const float* v    = (const float*)d_in[2];
    const int*   mask = (const int*)  d_in[3];

    const long long OUT_O_N = (long long)BB * HH * SS * DD;   // 8388608
    const long long OUT_S_N = (long long)BB * HH * SS * SS;   // 268435456

    float* o_ptr = 0;
    float* s_ptr = 0;
    if ((long long)out_size == OUT_O_N + OUT_S_N) {
        o_ptr = (float*)d_out;
        s_ptr = (float*)d_out + OUT_O_N;
    } else if ((long long)out_size == OUT_O_N) {
        o_ptr = (float*)d_out;
    } else if ((long long)out_size == OUT_S_N) {
        s_ptr = (float*)d_out;
    } else {
        o_ptr = (float*)d_out;   // fallback: at least produce the primary output
    }

    const int smem_bytes = SMEM_FLOATS * (int)sizeof(float);  // 106,496 B
    cudaFuncSetAttribute(attn_mma_kernel,
                         cudaFuncAttributeMaxDynamicSharedMemorySize, smem_bytes);

    dim3 grid(SS / BM, HH, BB);   // (16, 16, 4) = 1024 CTAs
    dim3 block(256);
    attn_mma_kernel<<<grid, block, smem_bytes>>>(q, k, v, mask, o_ptr, s_ptr);
}